// round 7
// baseline (speedup 1.0000x reference)
#include <cuda_runtime.h>
#include <cuda_bf16.h>
#include <cstdint>

#define NN  50000     // num nodes
#define EE  800000    // num edges
#define CC  64        // channels (in == out)
#define CAP 96        // per-node slot capacity (Poisson(16): P(deg>96) ~ 1e-50)
#define OVF_MAX 8192  // overflow edge buffer (correctness fallback)

// ---------------- scratch (no allocations allowed) ----------------
__device__ __align__(256) int   g_cnt[NN];          // degree / fill cursor
__device__ __align__(256) float g_dis[NN];          // clip(deg,1)^-1/2
__device__ __align__(256) int   g_slot[NN * CAP];   // src lists per target (19.2 MB)
__device__ __align__(256) int   g_ovf[OVF_MAX * 2]; // overflow (src,tgt) pairs
__device__ __align__(256) float g_agg[NN * CC];     // 12.8 MB aggregate
__device__ int g_novf;                              // overflow count
__device__ int g_is64;                              // 1 if edge_index is int64

// ---------------- kernel 1: zero counters + parallel dtype detect ----------------
__global__ void k_init(const void* __restrict__ edges, int E) {
    int i = blockIdx.x * blockDim.x + threadIdx.x;
    int stride = gridDim.x * blockDim.x;
    for (int k = i; k < NN; k += stride) g_cnt[k] = 0;
    if (i == 0) g_novf = 0;

    // int64 nonneg < 2^31  =>  every odd 32-bit word is zero.
    if (blockIdx.x == 0) {
        __shared__ int flag;
        if (threadIdx.x == 0) flag = 0;
        __syncthreads();
        if (threadIdx.x < 128) {
            const unsigned* w = reinterpret_cast<const unsigned*>(edges);
            int64_t pos = 2 * (int64_t)threadIdx.x + 1;
            if (pos < (int64_t)2 * E && w[pos] != 0u) atomicOr(&flag, 1);
        }
        __syncthreads();
        if (threadIdx.x == 0) g_is64 = (flag == 0);
    }
}

__device__ __forceinline__ int load_idx(const void* edges, int64_t pos, int is64) {
    if (is64) return (int)reinterpret_cast<const long long*>(edges)[pos];
    return reinterpret_cast<const int*>(edges)[pos];
}

// ---------------- kernel 2: fill slot table, 4 edges/thread (MLP=4) ----------------
__global__ void k_fill(const void* __restrict__ edges, int E) {
    int is64 = g_is64;
    int64_t base = ((int64_t)blockIdx.x * blockDim.x + threadIdx.x) * 4;
    if (base >= E) return;

    int src[4], tgt[4];
    int nv = 0;
#pragma unroll
    for (int j = 0; j < 4; j++) {
        int64_t i = base + j;
        if (i < E) {
            src[j] = load_idx(edges, i, is64);
            tgt[j] = load_idx(edges, (int64_t)E + i, is64);
            nv = j + 1;
        }
    }
    int pos[4];
#pragma unroll
    for (int j = 0; j < 4; j++)
        if (j < nv) pos[j] = atomicAdd(&g_cnt[tgt[j]], 1);
#pragma unroll
    for (int j = 0; j < 4; j++) {
        if (j < nv) {
            if (pos[j] < CAP) {
                g_slot[(int64_t)tgt[j] * CAP + pos[j]] = src[j];
            } else {
                int o = atomicAdd(&g_novf, 1);
                if (o < OVF_MAX) { g_ovf[2 * o] = src[j]; g_ovf[2 * o + 1] = tgt[j]; }
            }
        }
    }
}

// ---------------- kernel 3: deg_inv_sqrt ----------------
__global__ void k_dis(int n) {
    int i = blockIdx.x * blockDim.x + threadIdx.x;
    if (i >= n) return;
    g_dis[i] = rsqrtf(fmaxf((float)g_cnt[i], 1.0f));
}

// ---------------- kernel 4: gather-aggregate, no atomics (unchanged, proven) ----------------
__global__ __launch_bounds__(256) void k_agg(const float* __restrict__ x, int n) {
    int t  = blockIdx.x * blockDim.x + threadIdx.x;
    int nd = t >> 4;                  // node id
    int q  = threadIdx.x & 15;        // float4 slot in row
    if (nd >= n) return;

    int deg = g_cnt[nd];
    int d   = deg < CAP ? deg : CAP;
    float dt = g_dis[nd];
    const int* slots = g_slot + (int64_t)nd * CAP;
    const float4* x4 = reinterpret_cast<const float4*>(x);

    float4 acc = make_float4(0.f, 0.f, 0.f, 0.f);
    int e = 0;
    for (; e + 4 <= d; e += 4) {
        int s0 = slots[e + 0], s1 = slots[e + 1], s2 = slots[e + 2], s3 = slots[e + 3];
        float n0 = __ldg(&g_dis[s0]) * dt;
        float n1 = __ldg(&g_dis[s1]) * dt;
        float n2 = __ldg(&g_dis[s2]) * dt;
        float n3 = __ldg(&g_dis[s3]) * dt;
        float4 v0 = __ldg(&x4[(int64_t)s0 * 16 + q]);
        float4 v1 = __ldg(&x4[(int64_t)s1 * 16 + q]);
        float4 v2 = __ldg(&x4[(int64_t)s2 * 16 + q]);
        float4 v3 = __ldg(&x4[(int64_t)s3 * 16 + q]);
        acc.x += v0.x * n0 + v1.x * n1 + v2.x * n2 + v3.x * n3;
        acc.y += v0.y * n0 + v1.y * n1 + v2.y * n2 + v3.y * n3;
        acc.z += v0.z * n0 + v1.z * n1 + v2.z * n2 + v3.z * n3;
        acc.w += v0.w * n0 + v1.w * n1 + v2.w * n2 + v3.w * n3;
    }
    for (; e < d; e++) {
        int s = slots[e];
        float nm = __ldg(&g_dis[s]) * dt;
        float4 v = __ldg(&x4[(int64_t)s * 16 + q]);
        acc.x += v.x * nm; acc.y += v.y * nm; acc.z += v.z * nm; acc.w += v.w * nm;
    }

    reinterpret_cast<float4*>(g_agg)[(int64_t)nd * 16 + q] = acc;
}

// ---------------- kernel 5: overflow edges via RED atomics (rarely any) ----------------
__global__ void k_ovf(const float* __restrict__ x) {
    int novf = g_novf;
    int ne = novf < OVF_MAX ? novf : OVF_MAX;
    int t = blockIdx.x * blockDim.x + threadIdx.x;
    int e = t >> 4;
    int q = threadIdx.x & 15;
    if (e >= ne) return;
    int src = g_ovf[2 * e], tgt = g_ovf[2 * e + 1];
    float nm = g_dis[src] * g_dis[tgt];
    const float4* x4 = reinterpret_cast<const float4*>(x);
    float4 v = __ldg(&x4[(int64_t)src * 16 + q]);
    float* dst = g_agg + ((int64_t)tgt * CC + q * 4);
    asm volatile("red.global.add.v4.f32 [%0], {%1, %2, %3, %4};"
                 :: "l"(dst), "f"(v.x * nm), "f"(v.y * nm), "f"(v.z * nm), "f"(v.w * nm)
                 : "memory");
}

// ---------------- kernel 6: out = relu(agg @ W^T + b), packed f32x2 FMA ----------------
// Block 128 threads, 128 nodes/block. Thread (g = tid>>1, h = tid&1):
// nodes 2g, 2g+1; output pairs p in [h*16, h*16+16)  (outputs 2p, 2p+1).
// W staged in smem pair-interleaved: Wp[p][c] = (W[2p][c], W[2p+1][c]) as 64-bit.
__global__ __launch_bounds__(128) void k_gemm(const float* __restrict__ W,
                                              const float* __restrict__ b,
                                              float* __restrict__ out, int n) {
    __shared__ unsigned long long Wp[32 * 64];   // 16 KB
    __shared__ unsigned long long bp[32];

    for (int idx = threadIdx.x; idx < 32 * 64; idx += 128) {
        int p = idx >> 6, c = idx & 63;
        float w0 = W[(2 * p) * CC + c];
        float w1 = W[(2 * p + 1) * CC + c];
        unsigned long long v;
        asm("mov.b64 %0, {%1, %2};" : "=l"(v) : "f"(w0), "f"(w1));
        Wp[idx] = v;
    }
    if (threadIdx.x < 32) {
        unsigned long long v;
        asm("mov.b64 %0, {%1, %2};" : "=l"(v)
            : "f"(b[2 * threadIdx.x]), "f"(b[2 * threadIdx.x + 1]));
        bp[threadIdx.x] = v;
    }
    __syncthreads();

    int g  = threadIdx.x >> 1;
    int h  = threadIdx.x & 1;
    int nd0 = blockIdx.x * 128 + g * 2;
    if (nd0 >= n) return;
    int nd1 = nd0 + 1;
    bool has1 = nd1 < n;

    const float4* a0p = reinterpret_cast<const float4*>(g_agg + (int64_t)nd0 * CC);
    const float4* a1p = reinterpret_cast<const float4*>(g_agg + (int64_t)(has1 ? nd1 : nd0) * CC);

    unsigned long long acc0[16], acc1[16];
#pragma unroll
    for (int p = 0; p < 16; p++) {
        unsigned long long bv = bp[h * 16 + p];
        acc0[p] = bv; acc1[p] = bv;
    }

    const unsigned long long* wbase = Wp + (h * 16) * 64;

#pragma unroll 1
    for (int c4 = 0; c4 < 16; c4++) {
        float4 a0 = __ldg(a0p + c4);
        float4 a1 = __ldg(a1p + c4);
        float a0c[4] = {a0.x, a0.y, a0.z, a0.w};
        float a1c[4] = {a1.x, a1.y, a1.z, a1.w};
#pragma unroll
        for (int cc = 0; cc < 4; cc++) {
            unsigned long long a02, a12;
            asm("mov.b64 %0, {%1, %1};" : "=l"(a02) : "f"(a0c[cc]));
            asm("mov.b64 %0, {%1, %1};" : "=l"(a12) : "f"(a1c[cc]));
            const unsigned long long* wcol = wbase + c4 * 4 + cc;
#pragma unroll
            for (int p = 0; p < 16; p++) {
                unsigned long long wv = wcol[p * 64];
                asm("fma.rn.f32x2 %0, %1, %2, %0;" : "+l"(acc0[p]) : "l"(a02), "l"(wv));
                asm("fma.rn.f32x2 %0, %1, %2, %0;" : "+l"(acc1[p]) : "l"(a12), "l"(wv));
            }
        }
    }

    float* o0 = out + (int64_t)nd0 * CC;
    float* o1 = out + (int64_t)nd1 * CC;
#pragma unroll
    for (int p = 0; p < 16; p++) {
        int oidx = 2 * (h * 16 + p);
        float lo, hi;
        asm("mov.b64 {%0, %1}, %2;" : "=f"(lo), "=f"(hi) : "l"(acc0[p]));
        reinterpret_cast<float2*>(o0 + oidx)[0] = make_float2(fmaxf(lo, 0.f), fmaxf(hi, 0.f));
        if (has1) {
            asm("mov.b64 {%0, %1}, %2;" : "=f"(lo), "=f"(hi) : "l"(acc1[p]));
            reinterpret_cast<float2*>(o1 + oidx)[0] = make_float2(fmaxf(lo, 0.f), fmaxf(hi, 0.f));
        }
    }
}

// ---------------- launch ----------------
extern "C" void kernel_launch(void* const* d_in, const int* in_sizes, int n_in,
                              void* d_out, int out_size) {
    const float* x     = (const float*)d_in[0];
    const void*  edges = d_in[1];                 // int32 or int64, runtime-detected
    const float* W     = (const float*)d_in[2];
    const float* b     = (const float*)d_in[3];
    float* out = (float*)d_out;

    const int n = in_sizes[0] / CC;               // 50000
    const int E = in_sizes[1] / 2;                // 800000

    k_init<<<(NN + 255) / 256, 256>>>(edges, E);
    k_fill<<<(E + 1023) / 1024, 256>>>(edges, E);
    k_dis<<<(n + 255) / 256, 256>>>(n);
    {
        int64_t threads = (int64_t)n * 16;
        int blocks = (int)((threads + 255) / 256);
        k_agg<<<blocks, 256>>>(x, n);
    }
    k_ovf<<<(OVF_MAX * 16 + 255) / 256, 256>>>(x);
    k_gemm<<<(n + 127) / 128, 128>>>(W, b, out, n);
}

// round 12
// speedup vs baseline: 1.0590x; 1.0590x over previous
#include <cuda_runtime.h>
#include <cuda_fp16.h>
#include <cstdint>

#define NN  50000     // num nodes
#define EE  800000    // num edges
#define CC  64        // channels (in == out)
#define CAP 96        // per-node slot capacity (Poisson(16): P(deg>96) ~ 1e-50)
#define OVF_MAX 8192  // overflow edge buffer (correctness fallback)
#define PAD 8         // counter padding stride (32 B) to spread LTS atomic hash

// ---------------- scratch (no allocations; zero-initialized at module load) ----
__device__ __align__(256) int    g_cntp[NN * PAD];   // padded degree/cursor (1.6 MB)
__device__ __align__(256) float  g_dis[NN];          // clip(deg,1)^-1/2
__device__ __align__(256) __half g_xh[NN * CC];      // fp16 mirror of x (6.4 MB)
__device__ __align__(256) int    g_slot[NN * CAP];   // src lists per target (19.2 MB)
__device__ __align__(256) int    g_ovf[OVF_MAX * 2]; // overflow (src,tgt) pairs
__device__ __align__(256) float  g_agg[NN * CC];     // 12.8 MB aggregate
__device__ int g_novf;                               // overflow count

__device__ __forceinline__ int load_idx(const void* edges, int64_t pos, int is64) {
    if (is64) return (int)reinterpret_cast<const long long*>(edges)[pos];
    return reinterpret_cast<const int*>(edges)[pos];
}

// ---------------- kernel 1: fill slot table (inline dtype detect, 4 edges/thread) --
__global__ void k_fill(const void* __restrict__ edges, int E) {
    // Per-block dtype detect: int64 nonneg < 2^31 => all odd 32-bit words zero.
    // First 1 KB of edges is L2-resident after block 0; cost ~nil.
    __shared__ int sflag;
    if (threadIdx.x == 0) sflag = 0;
    __syncthreads();
    if (threadIdx.x < 128) {
        const unsigned* w = reinterpret_cast<const unsigned*>(edges);
        int64_t p = 2 * (int64_t)threadIdx.x + 1;
        if (p < 2 * (int64_t)E && w[p] != 0u) atomicOr(&sflag, 1);
    }
    __syncthreads();
    int is64 = (sflag == 0);

    int64_t base = ((int64_t)blockIdx.x * blockDim.x + threadIdx.x) * 4;
    if (base >= E) return;

    int src[4], tgt[4];
    int nv = 0;
#pragma unroll
    for (int j = 0; j < 4; j++) {
        int64_t i = base + j;
        if (i < E) {
            src[j] = load_idx(edges, i, is64);
            tgt[j] = load_idx(edges, (int64_t)E + i, is64);
            nv = j + 1;
        }
    }
    int pos[4];
#pragma unroll
    for (int j = 0; j < 4; j++)
        if (j < nv) pos[j] = atomicAdd(&g_cntp[tgt[j] * PAD], 1);
#pragma unroll
    for (int j = 0; j < 4; j++) {
        if (j < nv) {
            if (pos[j] < CAP) {
                g_slot[(int64_t)tgt[j] * CAP + pos[j]] = src[j];
            } else {
                int o = atomicAdd(&g_novf, 1);
                if (o < OVF_MAX) { g_ovf[2 * o] = src[j]; g_ovf[2 * o + 1] = tgt[j]; }
            }
        }
    }
}

// ---------------- kernel 2: deg_inv_sqrt + fp16 mirror of x ----------------
__global__ void k_prep(const float* __restrict__ x, int n) {
    int i = blockIdx.x * blockDim.x + threadIdx.x;
    if (i < n) g_dis[i] = rsqrtf(fmaxf((float)g_cntp[i * PAD], 1.0f));

    const float2* x2 = reinterpret_cast<const float2*>(x);
    __half2* xh2 = reinterpret_cast<__half2*>(g_xh);
    int total = n * (CC / 2);
    int stride = gridDim.x * blockDim.x;
    for (int k = i; k < total; k += stride)
        xh2[k] = __float22half2_rn(x2[k]);
}

// ---------------- kernel 3: gather-aggregate (fp16 gathers, no atomics) ------
// Half-warp (16 lanes) per target node; lane q owns channels [4q, 4q+4).
// 4-wide edge unroll => 4 independent src->xh load chains in flight.
__global__ __launch_bounds__(256) void k_agg(const float* __restrict__ x, int n) {
    int t  = blockIdx.x * blockDim.x + threadIdx.x;
    int nd = t >> 4;
    int q  = threadIdx.x & 15;
    if (nd >= n) return;

    int deg = g_cntp[nd * PAD];
    int d   = deg < CAP ? deg : CAP;
    float dt = g_dis[nd];
    const int* slots = g_slot + (int64_t)nd * CAP;
    const uint2* xh = reinterpret_cast<const uint2*>(g_xh);   // 8 B = 4 halves/lane

    float4 acc = make_float4(0.f, 0.f, 0.f, 0.f);
    int e = 0;
    for (; e + 4 <= d; e += 4) {
        int s0 = slots[e + 0], s1 = slots[e + 1], s2 = slots[e + 2], s3 = slots[e + 3];
        float n0 = __ldg(&g_dis[s0]) * dt;
        float n1 = __ldg(&g_dis[s1]) * dt;
        float n2 = __ldg(&g_dis[s2]) * dt;
        float n3 = __ldg(&g_dis[s3]) * dt;
        uint2 r0 = __ldg(&xh[(int64_t)s0 * 16 + q]);
        uint2 r1 = __ldg(&xh[(int64_t)s1 * 16 + q]);
        uint2 r2 = __ldg(&xh[(int64_t)s2 * 16 + q]);
        uint2 r3 = __ldg(&xh[(int64_t)s3 * 16 + q]);
        {
            float2 fa = __half22float2(*reinterpret_cast<__half2*>(&r0.x));
            float2 fb = __half22float2(*reinterpret_cast<__half2*>(&r0.y));
            acc.x += fa.x * n0; acc.y += fa.y * n0; acc.z += fb.x * n0; acc.w += fb.y * n0;
        }
        {
            float2 fa = __half22float2(*reinterpret_cast<__half2*>(&r1.x));
            float2 fb = __half22float2(*reinterpret_cast<__half2*>(&r1.y));
            acc.x += fa.x * n1; acc.y += fa.y * n1; acc.z += fb.x * n1; acc.w += fb.y * n1;
        }
        {
            float2 fa = __half22float2(*reinterpret_cast<__half2*>(&r2.x));
            float2 fb = __half22float2(*reinterpret_cast<__half2*>(&r2.y));
            acc.x += fa.x * n2; acc.y += fa.y * n2; acc.z += fb.x * n2; acc.w += fb.y * n2;
        }
        {
            float2 fa = __half22float2(*reinterpret_cast<__half2*>(&r3.x));
            float2 fb = __half22float2(*reinterpret_cast<__half2*>(&r3.y));
            acc.x += fa.x * n3; acc.y += fa.y * n3; acc.z += fb.x * n3; acc.w += fb.y * n3;
        }
    }
    for (; e < d; e++) {
        int s = slots[e];
        float nm = __ldg(&g_dis[s]) * dt;
        uint2 r = __ldg(&xh[(int64_t)s * 16 + q]);
        float2 fa = __half22float2(*reinterpret_cast<__half2*>(&r.x));
        float2 fb = __half22float2(*reinterpret_cast<__half2*>(&r.y));
        acc.x += fa.x * nm; acc.y += fa.y * nm; acc.z += fb.x * nm; acc.w += fb.y * nm;
    }

    // Cold overflow path (novf == 0 for any non-degenerate graph): one uniform
    // cached load; full-precision fp32 gathers if ever taken.
    int novf = g_novf;
    if (novf > 0) {
        int ne = novf < OVF_MAX ? novf : OVF_MAX;
        const float4* x4 = reinterpret_cast<const float4*>(x);
        for (int o = 0; o < ne; o++) {
            if (g_ovf[2 * o + 1] == nd) {
                int s = g_ovf[2 * o];
                float nm = g_dis[s] * dt;
                float4 v = __ldg(&x4[(int64_t)s * 16 + q]);
                acc.x += v.x * nm; acc.y += v.y * nm; acc.z += v.z * nm; acc.w += v.w * nm;
            }
        }
    }

    reinterpret_cast<float4*>(g_agg)[(int64_t)nd * 16 + q] = acc;
}

// ---------------- kernel 4: out = relu(agg @ W^T + b)  [R6-proven] + cleanup --
__global__ __launch_bounds__(256) void k_gemm(const float* __restrict__ W,
                                              const float* __restrict__ b,
                                              float* __restrict__ out, int n) {
    // Reset per-invocation state for the NEXT run (globals start zeroed at load,
    // so the invariant "counters zero at k_fill entry" holds for every call).
    int tix = blockIdx.x * blockDim.x + threadIdx.x;
    if (tix < NN) g_cntp[tix * PAD] = 0;
    if (tix == 0) g_novf = 0;

    __shared__ float Ws[CC * CC];
    __shared__ float bs[CC];
    for (int i = threadIdx.x; i < CC * CC; i += blockDim.x) Ws[i] = W[i];
    if (threadIdx.x < CC) bs[threadIdx.x] = b[threadIdx.x];
    __syncthreads();

    int node = tix;
    if (node >= n) return;

    float4 a[16];
    const float4* arow = reinterpret_cast<const float4*>(g_agg + (int64_t)node * CC);
#pragma unroll
    for (int i = 0; i < 16; i++) a[i] = arow[i];

    float4* orow = reinterpret_cast<float4*>(out + (int64_t)node * CC);
    const float4* Ws4 = reinterpret_cast<const float4*>(Ws);

#pragma unroll
    for (int o = 0; o < CC; o += 4) {
        float acc0 = bs[o + 0], acc1 = bs[o + 1], acc2 = bs[o + 2], acc3 = bs[o + 3];
#pragma unroll
        for (int c = 0; c < 16; c++) {
            float4 av = a[c];
            float4 w0 = Ws4[(o + 0) * 16 + c];
            float4 w1 = Ws4[(o + 1) * 16 + c];
            float4 w2 = Ws4[(o + 2) * 16 + c];
            float4 w3 = Ws4[(o + 3) * 16 + c];
            acc0 += av.x * w0.x + av.y * w0.y + av.z * w0.z + av.w * w0.w;
            acc1 += av.x * w1.x + av.y * w1.y + av.z * w1.z + av.w * w1.w;
            acc2 += av.x * w2.x + av.y * w2.y + av.z * w2.z + av.w * w2.w;
            acc3 += av.x * w3.x + av.y * w3.y + av.z * w3.z + av.w * w3.w;
        }
        float4 r;
        r.x = fmaxf(acc0, 0.f);
        r.y = fmaxf(acc1, 0.f);
        r.z = fmaxf(acc2, 0.f);
        r.w = fmaxf(acc3, 0.f);
        orow[o >> 2] = r;
    }
}

// ---------------- launch (4 kernels) ----------------
extern "C" void kernel_launch(void* const* d_in, const int* in_sizes, int n_in,
                              void* d_out, int out_size) {
    const float* x     = (const float*)d_in[0];
    const void*  edges = d_in[1];                 // int32 or int64, runtime-detected
    const float* W     = (const float*)d_in[2];
    const float* b     = (const float*)d_in[3];
    float* out = (float*)d_out;

    const int n = in_sizes[0] / CC;               // 50000
    const int E = in_sizes[1] / 2;                // 800000

    k_fill<<<(E + 1023) / 1024, 256>>>(edges, E);
    k_prep<<<(n * (CC / 2) + 255) / 256, 256>>>(x, n);
    {
        int64_t threads = (int64_t)n * 16;
        int blocks = (int)((threads + 255) / 256);
        k_agg<<<blocks, 256>>>(x, n);
    }
    k_gemm<<<(n + 255) / 256, 256>>>(W, b, out, n);
}